// round 6
// baseline (speedup 1.0000x reference)
#include <cuda_runtime.h>
#include <cuda_bf16.h>
#include <cstdint>

// out[128,1024] = x[128,1024] @ (w_pos - w_neg)[1024,1024] + (b_pos - b_neg)
// Memristor scaling cancels exactly (G_OFF in the differential pair, k_cond &
// K_V in the rescale; max_w never needed).
// 3-term bf16 hi/lo emulation on HMMA (baseline PTX mma.sync):
//   x = xh+xl, d = dh+dl;  out ~= xh@dh + xh@dl + xl@dh   (xl@dl ~2^-16)
//
// Round 6: conversion moved OFF the GEMM critical path. Prep kernel streams
// wp,wn -> dh,dl (bf16), x -> xh,xl (bf16), bias diff -> out. GEMM is lean:
// cp.async raw bf16 tiles (B from L2 -- just written), ldmatrix, MMA, REDG.

#define BATCH 128
#define NIN   1024
#define NOUT  1024
#define KSPLIT 32
#define KCHUNK 32       // NIN / KSPLIT
#define TILE_N 64
#define NT 16           // NOUT / TILE_N
#define RA 80           // A smem row stride bytes (32 bf16 = 64B + 16 pad)
#define RB 144          // B smem row stride bytes (64 bf16 = 128B + 16 pad)

// pre-split operands (bf16), written by prep kernel
__device__ __nv_bfloat16 g_dh[NIN * NOUT];   // 2 MB
__device__ __nv_bfloat16 g_dl[NIN * NOUT];   // 2 MB
__device__ __nv_bfloat16 g_xh[BATCH * NIN];  // 256 KB
__device__ __nv_bfloat16 g_xl[BATCH * NIN];  // 256 KB

__device__ __forceinline__ uint32_t smem_u32(const void* p) {
    uint32_t a;
    asm("{ .reg .u64 t; cvta.to.shared.u64 t, %1; cvt.u32.u64 %0, t; }" : "=r"(a) : "l"(p));
    return a;
}
__device__ __forceinline__ void split_hl(float v, uint16_t& h, uint16_t& l) {
    __nv_bfloat16 bh = __float2bfloat16(v);
    h = __bfloat16_as_ushort(bh);
    float r = v - __bfloat162float(bh);
    l = __bfloat16_as_ushort(__float2bfloat16(r));
}
__device__ __forceinline__ void ldsm4(uint32_t* r, uint32_t a) {
    asm volatile("ldmatrix.sync.aligned.m8n8.x4.shared.b16 {%0,%1,%2,%3}, [%4];"
                 : "=r"(r[0]), "=r"(r[1]), "=r"(r[2]), "=r"(r[3]) : "r"(a));
}
__device__ __forceinline__ void ldsm4t(uint32_t* r, uint32_t a) {
    asm volatile("ldmatrix.sync.aligned.m8n8.x4.trans.shared.b16 {%0,%1,%2,%3}, [%4];"
                 : "=r"(r[0]), "=r"(r[1]), "=r"(r[2]), "=r"(r[3]) : "r"(a));
}
__device__ __forceinline__ void mma16816(float* d, const uint32_t* a,
                                         uint32_t b0, uint32_t b1) {
    asm volatile("mma.sync.aligned.m16n8k16.row.col.f32.bf16.bf16.f32 "
                 "{%0,%1,%2,%3}, {%4,%5,%6,%7}, {%8,%9}, {%0,%1,%2,%3};"
                 : "+f"(d[0]), "+f"(d[1]), "+f"(d[2]), "+f"(d[3])
                 : "r"(a[0]), "r"(a[1]), "r"(a[2]), "r"(a[3]), "r"(b0), "r"(b1));
}
__device__ __forceinline__ void red_add_v2(float* p, float a, float b) {
    asm volatile("red.global.add.v2.f32 [%0], {%1, %2};"
                 :: "l"(p), "f"(a), "f"(b) : "memory");
}
__device__ __forceinline__ void cp_async16(uint32_t dst, const void* src) {
    asm volatile("cp.async.ca.shared.global [%0], [%1], 16;"
                 :: "r"(dst), "l"(src) : "memory");
}
__device__ __forceinline__ uint64_t pack4(uint16_t a, uint16_t b, uint16_t c, uint16_t d) {
    return (uint64_t)a | ((uint64_t)b << 16) | ((uint64_t)c << 32) | ((uint64_t)d << 48);
}

// ---- prep: split W diff and x into bf16 hi/lo; write bias diff into out ----
extern "C" __global__ void __launch_bounds__(256)
memr_prep(const float* __restrict__ x,
          const float* __restrict__ wp,
          const float* __restrict__ wn,
          const float* __restrict__ bp,
          const float* __restrict__ bn,
          float* __restrict__ out) {
    const int bid = blockIdx.x;
    const int t   = threadIdx.x;
    if (bid < 1024) {
        // W: 1M elements as 262144 float4
        size_t base = ((size_t)bid * 256 + t) * 4;
        float4 p = *reinterpret_cast<const float4*>(wp + base);
        float4 n = *reinterpret_cast<const float4*>(wn + base);
        uint16_t h0, h1, h2, h3, l0, l1, l2, l3;
        split_hl(p.x - n.x, h0, l0); split_hl(p.y - n.y, h1, l1);
        split_hl(p.z - n.z, h2, l2); split_hl(p.w - n.w, h3, l3);
        *reinterpret_cast<uint64_t*>(g_dh + base) = pack4(h0, h1, h2, h3);
        *reinterpret_cast<uint64_t*>(g_dl + base) = pack4(l0, l1, l2, l3);
    } else if (bid < 1152) {
        // x: 131072 floats as 32768 float4
        size_t base = ((size_t)(bid - 1024) * 256 + t) * 4;
        float4 v = *reinterpret_cast<const float4*>(x + base);
        uint16_t h0, h1, h2, h3, l0, l1, l2, l3;
        split_hl(v.x, h0, l0); split_hl(v.y, h1, l1);
        split_hl(v.z, h2, l2); split_hl(v.w, h3, l3);
        *reinterpret_cast<uint64_t*>(g_xh + base) = pack4(h0, h1, h2, h3);
        *reinterpret_cast<uint64_t*>(g_xl + base) = pack4(l0, l1, l2, l3);
    } else {
        // bias diff broadcast: 131072 out floats as 32768 float4
        size_t base = ((size_t)(bid - 1152) * 256 + t) * 4;
        int o = (int)(base & (NOUT - 1));
        float4 vp = *reinterpret_cast<const float4*>(bp + o);
        float4 vn = *reinterpret_cast<const float4*>(bn + o);
        *reinterpret_cast<float4*>(out + base) =
            make_float4(vp.x - vn.x, vp.y - vn.y, vp.z - vn.z, vp.w - vn.w);
    }
}

// ---- GEMM: grid (16 NT, 32 KSPLIT); CTA tile 128M x 64N x 32K ----
extern "C" __global__ void __launch_bounds__(256, 3)
memr_gemm_hmma(float* __restrict__ out) {
    extern __shared__ char smem_raw[];
    const uint32_t Ah = smem_u32(smem_raw);       // xh [128 b][32 k]
    const uint32_t Al = Ah + 128 * RA;            // xl
    const uint32_t Bh = Al + 128 * RA;            // dh [32 k][64 o]
    const uint32_t Bl = Bh + 32 * RB;             // dl

    const int t  = threadIdx.x;
    const int jt = blockIdx.x;
    const int ks = blockIdx.y;
    const int k0 = ks * KCHUNK;
    const int j0 = jt * TILE_N;

    // ---- A tiles: 1024 x 16B chunks (Ah 512 + Al 512), 4 per thread ----
#pragma unroll
    for (int i = 0; i < 4; i++) {
        int id = t + 256 * i;
        int c   = id & 511;           // chunk within one matrix
        int row = c >> 2;             // 4 chunks per 64B row
        int ch  = c & 3;
        uint32_t dst = (id < 512 ? Ah : Al) + (uint32_t)row * RA + (uint32_t)ch * 16;
        const __nv_bfloat16* src =
            (id < 512 ? g_xh : g_xl) + (size_t)row * NIN + k0 + ch * 8;
        cp_async16(dst, src);
    }
    // ---- B tiles: 512 x 16B chunks (Bh 256 + Bl 256), 2 per thread ----
#pragma unroll
    for (int i = 0; i < 2; i++) {
        int id = t + 256 * i;
        int c    = id & 255;
        int krow = c >> 3;            // 8 chunks per 128B row
        int ch   = c & 7;
        uint32_t dst = (id < 256 ? Bh : Bl) + (uint32_t)krow * RB + (uint32_t)ch * 16;
        const __nv_bfloat16* src =
            (id < 256 ? g_dh : g_dl) + (size_t)(k0 + krow) * NOUT + j0 + ch * 8;
        cp_async16(dst, src);
    }
    asm volatile("cp.async.commit_group;" ::: "memory");
    asm volatile("cp.async.wait_group 0;" ::: "memory");
    __syncthreads();

    // ---- compute: 8 warps as 4(M) x 2(N); warp tile 32 rows x 32 cols ----
    const int wid  = t >> 5;
    const int lane = t & 31;
    const int wm  = wid >> 1;
    const int wn2 = wid & 1;

    float acc[2][4][4];
#pragma unroll
    for (int mt = 0; mt < 2; mt++)
#pragma unroll
        for (int n = 0; n < 4; n++)
#pragma unroll
            for (int i = 0; i < 4; i++) acc[mt][n][i] = 0.0f;

    const uint32_t aOff = (uint32_t)(wm * 32 + (lane & 15)) * RA + (uint32_t)((lane >> 4) * 16);
    const uint32_t bOff = (uint32_t)(lane & 15) * RB + (uint32_t)(wn2 * 32 + (lane >> 4) * 8) * 2;
    const uint32_t aH = Ah + aOff, aL = Al + aOff;
    const uint32_t bH = Bh + bOff, bL = Bl + bOff;

#pragma unroll
    for (int s = 0; s < 2; s++) {
        const uint32_t soA = (uint32_t)s * 32;        // 16 bf16 along k
        const uint32_t soB = (uint32_t)(s * 16) * RB; // 16 k-rows down
        uint32_t ah[2][4], al[2][4];
        ldsm4(ah[0], aH + soA);
        ldsm4(ah[1], aH + 16 * RA + soA);
        ldsm4(al[0], aL + soA);
        ldsm4(al[1], aL + 16 * RA + soA);
        uint32_t bhr[2][4], blr[2][4];
        ldsm4t(bhr[0], bH + soB);
        ldsm4t(bhr[1], bH + soB + 32);    // cols +16
        ldsm4t(blr[0], bL + soB);
        ldsm4t(blr[1], bL + soB + 32);
#pragma unroll
        for (int n = 0; n < 4; n++) {
            const int g = n >> 1, j = n & 1;
            const uint32_t b0h = bhr[g][2 * j], b1h = bhr[g][2 * j + 1];
            const uint32_t b0l = blr[g][2 * j], b1l = blr[g][2 * j + 1];
#pragma unroll
            for (int mt = 0; mt < 2; mt++) {
                mma16816(acc[mt][n], ah[mt], b0h, b1h);
                mma16816(acc[mt][n], ah[mt], b0l, b1l);
                mma16816(acc[mt][n], al[mt], b0h, b1h);
            }
        }
    }

    // ---- epilogue: accumulate warp block 32x32 into out via red.v2 ----
    const int r0 = wm * 32 + (lane >> 2);
    const int c0 = j0 + wn2 * 32 + 2 * (lane & 3);
#pragma unroll
    for (int mt = 0; mt < 2; mt++) {
#pragma unroll
        for (int n = 0; n < 4; n++) {
            int row = r0 + mt * 16;
            int col = c0 + n * 8;
            red_add_v2(out + (size_t)row * NOUT + col, acc[mt][n][0], acc[mt][n][1]);
            red_add_v2(out + (size_t)(row + 8) * NOUT + col, acc[mt][n][2], acc[mt][n][3]);
        }
    }
}

extern "C" void kernel_launch(void* const* d_in, const int* in_sizes, int n_in,
                              void* d_out, int out_size) {
    const float* x  = (const float*)d_in[0];
    const float* wp = (const float*)d_in[1];
    const float* wn = (const float*)d_in[2];
    const float* bp = (const float*)d_in[3];
    const float* bn = (const float*)d_in[4];
    float* out = (float*)d_out;

    const int smem_bytes = 2 * 128 * RA + 2 * 32 * RB;   // 29696
    memr_prep<<<1280, 256>>>(x, wp, wn, bp, bn, out);
    dim3 grid(NT, KSPLIT);
    memr_gemm_hmma<<<grid, 256, smem_bytes>>>(out);
}

// round 8
// speedup vs baseline: 1.1575x; 1.1575x over previous
#include <cuda_runtime.h>
#include <cuda_bf16.h>
#include <cstdint>

// out[128,1024] = x[128,1024] @ (w_pos - w_neg)[1024,1024] + (b_pos - b_neg)
// Memristor scaling cancels exactly (G_OFF in the differential pair, k_cond &
// K_V in the rescale; max_w never needed).
// 3-term bf16 hi/lo emulation on HMMA (baseline PTX mma.sync):
//   x = xh+xl, d = dh+dl;  out ~= xh@dh + xh@dl + xl@dh   (xl@dl ~2^-16)
//
// Round 7: proper double-buffered pipelined GEMM. CTA tile 32M x 64N x 512K
// streamed in 8 stages of k=64 with cp.async prefetch overlapping compute.
// Grid 16N x 4M x 2Ksplit = 128 CTAs (one wave). Epilogue red.global.add.v2
// (2 writers/address). Prep kernel pre-splits operands to bf16 hi/lo.

#define BATCH 128
#define NIN   1024
#define NOUT  1024
#define MT    32          // M per CTA
#define TILE_N 64
#define KSPLIT 2
#define KPER  512         // K per CTA
#define KC    64          // k per stage
#define NSTAGE 8          // KPER / KC
#define RS    144         // smem row stride bytes (128B data + 16 pad)
#define A_STG (32 * RS)          // 4608 per h/l
#define B_STG (64 * RS)          // 9216 per h/l
#define STAGE_BYTES (2 * A_STG + 2 * B_STG)   // 27648

// pre-split operands (bf16), written by prep kernel
__device__ __nv_bfloat16 g_dh[NIN * NOUT];
__device__ __nv_bfloat16 g_dl[NIN * NOUT];
__device__ __nv_bfloat16 g_xh[BATCH * NIN];
__device__ __nv_bfloat16 g_xl[BATCH * NIN];

__device__ __forceinline__ uint32_t smem_u32(const void* p) {
    uint32_t a;
    asm("{ .reg .u64 t; cvta.to.shared.u64 t, %1; cvt.u32.u64 %0, t; }" : "=r"(a) : "l"(p));
    return a;
}
__device__ __forceinline__ void split_hl(float v, uint16_t& h, uint16_t& l) {
    __nv_bfloat16 bh = __float2bfloat16(v);
    h = __bfloat16_as_ushort(bh);
    float r = v - __bfloat162float(bh);
    l = __bfloat16_as_ushort(__float2bfloat16(r));
}
__device__ __forceinline__ void ldsm4(uint32_t* r, uint32_t a) {
    asm volatile("ldmatrix.sync.aligned.m8n8.x4.shared.b16 {%0,%1,%2,%3}, [%4];"
                 : "=r"(r[0]), "=r"(r[1]), "=r"(r[2]), "=r"(r[3]) : "r"(a));
}
__device__ __forceinline__ void ldsm4t(uint32_t* r, uint32_t a) {
    asm volatile("ldmatrix.sync.aligned.m8n8.x4.trans.shared.b16 {%0,%1,%2,%3}, [%4];"
                 : "=r"(r[0]), "=r"(r[1]), "=r"(r[2]), "=r"(r[3]) : "r"(a));
}
__device__ __forceinline__ void mma16816(float* d, const uint32_t* a,
                                         uint32_t b0, uint32_t b1) {
    asm volatile("mma.sync.aligned.m16n8k16.row.col.f32.bf16.bf16.f32 "
                 "{%0,%1,%2,%3}, {%4,%5,%6,%7}, {%8,%9}, {%0,%1,%2,%3};"
                 : "+f"(d[0]), "+f"(d[1]), "+f"(d[2]), "+f"(d[3])
                 : "r"(a[0]), "r"(a[1]), "r"(a[2]), "r"(a[3]), "r"(b0), "r"(b1));
}
__device__ __forceinline__ void red_add_v2(float* p, float a, float b) {
    asm volatile("red.global.add.v2.f32 [%0], {%1, %2};"
                 :: "l"(p), "f"(a), "f"(b) : "memory");
}
__device__ __forceinline__ void cp_async16(uint32_t dst, const void* src) {
    asm volatile("cp.async.cg.shared.global [%0], [%1], 16;"
                 :: "r"(dst), "l"(src) : "memory");
}
__device__ __forceinline__ uint64_t pack4(uint16_t a, uint16_t b, uint16_t c, uint16_t d) {
    return (uint64_t)a | ((uint64_t)b << 16) | ((uint64_t)c << 32) | ((uint64_t)d << 48);
}

// ---- prep: split W diff and x into bf16 hi/lo; write bias diff into out ----
extern "C" __global__ void __launch_bounds__(256)
memr_prep(const float* __restrict__ x,
          const float* __restrict__ wp,
          const float* __restrict__ wn,
          const float* __restrict__ bp,
          const float* __restrict__ bn,
          float* __restrict__ out) {
    const int bid = blockIdx.x;
    const int t   = threadIdx.x;
    if (bid < 1024) {
        size_t base = ((size_t)bid * 256 + t) * 4;
        float4 p = *reinterpret_cast<const float4*>(wp + base);
        float4 n = *reinterpret_cast<const float4*>(wn + base);
        uint16_t h0, h1, h2, h3, l0, l1, l2, l3;
        split_hl(p.x - n.x, h0, l0); split_hl(p.y - n.y, h1, l1);
        split_hl(p.z - n.z, h2, l2); split_hl(p.w - n.w, h3, l3);
        *reinterpret_cast<uint64_t*>(g_dh + base) = pack4(h0, h1, h2, h3);
        *reinterpret_cast<uint64_t*>(g_dl + base) = pack4(l0, l1, l2, l3);
    } else if (bid < 1152) {
        size_t base = ((size_t)(bid - 1024) * 256 + t) * 4;
        float4 v = *reinterpret_cast<const float4*>(x + base);
        uint16_t h0, h1, h2, h3, l0, l1, l2, l3;
        split_hl(v.x, h0, l0); split_hl(v.y, h1, l1);
        split_hl(v.z, h2, l2); split_hl(v.w, h3, l3);
        *reinterpret_cast<uint64_t*>(g_xh + base) = pack4(h0, h1, h2, h3);
        *reinterpret_cast<uint64_t*>(g_xl + base) = pack4(l0, l1, l2, l3);
    } else {
        size_t base = ((size_t)(bid - 1152) * 256 + t) * 4;
        int o = (int)(base & (NOUT - 1));
        float4 vp = *reinterpret_cast<const float4*>(bp + o);
        float4 vn = *reinterpret_cast<const float4*>(bn + o);
        *reinterpret_cast<float4*>(out + base) =
            make_float4(vp.x - vn.x, vp.y - vn.y, vp.z - vn.z, vp.w - vn.w);
    }
}

// ---- pipelined GEMM ----
extern "C" __global__ void __launch_bounds__(256, 1)
memr_gemm_hmma(float* __restrict__ out) {
    extern __shared__ char smem_raw[];
    const uint32_t base = smem_u32(smem_raw);

    const int t    = threadIdx.x;
    const int wid  = t >> 5;
    const int lane = t & 31;
    const int j0 = blockIdx.x * TILE_N;
    const int m0 = blockIdx.y * MT;
    const int k0 = blockIdx.z * KPER;

    // stage loader: fills buf with A(h,l) 32x64k and B(h,l) 64k x 64o
    auto issue_stage = [&](int s, int buf) {
        const uint32_t sb = base + (uint32_t)buf * STAGE_BYTES;
        const int kb = k0 + s * KC;
        // A: 512 x 16B chunks (h then l); 2 per thread
#pragma unroll
        for (int i = 0; i < 2; i++) {
            int id  = t + 256 * i;
            int hl  = id >> 8;
            int c   = id & 255;
            int row = c >> 3;          // 32 rows, 8 chunks each
            int ch  = c & 7;
            uint32_t dst = sb + (uint32_t)hl * A_STG + (uint32_t)row * RS + (uint32_t)ch * 16;
            const __nv_bfloat16* src =
                (hl ? g_xl : g_xh) + (size_t)(m0 + row) * NIN + kb + ch * 8;
            cp_async16(dst, src);
        }
        // B: 1024 x 16B chunks (h then l); 4 per thread
#pragma unroll
        for (int i = 0; i < 4; i++) {
            int id  = t + 256 * i;
            int hl  = id >> 9;
            int c   = id & 511;
            int row = c >> 3;          // 64 k-rows, 8 chunks each
            int ch  = c & 7;
            uint32_t dst = sb + 2 * A_STG + (uint32_t)hl * B_STG +
                           (uint32_t)row * RS + (uint32_t)ch * 16;
            const __nv_bfloat16* src =
                (hl ? g_dl : g_dh) + (size_t)(kb + row) * NOUT + j0 + ch * 8;
            cp_async16(dst, src);
        }
        asm volatile("cp.async.commit_group;" ::: "memory");
    };

    // warp tiling: 8 warps = 2(M,16) x 4(N,16)
    const int wm  = wid >> 2;
    const int wn2 = wid & 3;
    const uint32_t aOff = (uint32_t)(wm * 16 + (lane & 15)) * RS + (uint32_t)((lane >> 4) * 16);
    const uint32_t bOff = (uint32_t)(lane & 15) * RS + (uint32_t)(wn2 * 16 + (lane >> 4) * 8) * 2;

    float acc[2][4];
#pragma unroll
    for (int n = 0; n < 2; n++)
#pragma unroll
        for (int i = 0; i < 4; i++) acc[n][i] = 0.0f;

    issue_stage(0, 0);

#pragma unroll
    for (int s = 0; s < NSTAGE; s++) {
        if (s + 1 < NSTAGE) {
            issue_stage(s + 1, (s + 1) & 1);
            asm volatile("cp.async.wait_group 1;" ::: "memory");
        } else {
            asm volatile("cp.async.wait_group 0;" ::: "memory");
        }
        __syncthreads();

        const uint32_t sb = base + (uint32_t)(s & 1) * STAGE_BYTES;
        const uint32_t aH = sb + aOff;
        const uint32_t aL = sb + A_STG + aOff;
        const uint32_t bH = sb + 2 * A_STG + bOff;
        const uint32_t bL = sb + 2 * A_STG + B_STG + bOff;

#pragma unroll
        for (int q = 0; q < 4; q++) {           // 4 k16-steps per stage
            const uint32_t soA = (uint32_t)q * 32;
            const uint32_t soB = (uint32_t)(q * 16) * RS;
            uint32_t ah[4], al[4], bh[4], bl[4];
            ldsm4 (ah, aH + soA);
            ldsm4 (al, aL + soA);
            ldsm4t(bh, bH + soB);
            ldsm4t(bl, bL + soB);
#pragma unroll
            for (int n = 0; n < 2; n++) {
                mma16816(acc[n], ah, bh[2 * n], bh[2 * n + 1]);
                mma16816(acc[n], ah, bl[2 * n], bl[2 * n + 1]);
                mma16816(acc[n], al, bh[2 * n], bh[2 * n + 1]);
            }
        }
        __syncthreads();
    }

    // ---- epilogue: red.v2 into out (2 writers per address) ----
    const int r0 = m0 + wm * 16 + (lane >> 2);
    const int c0 = j0 + wn2 * 16 + 2 * (lane & 3);
#pragma unroll
    for (int n = 0; n < 2; n++) {
        red_add_v2(out + (size_t)r0 * NOUT + c0 + n * 8, acc[n][0], acc[n][1]);
        red_add_v2(out + (size_t)(r0 + 8) * NOUT + c0 + n * 8, acc[n][2], acc[n][3]);
    }
}

extern "C" void kernel_launch(void* const* d_in, const int* in_sizes, int n_in,
                              void* d_out, int out_size) {
    const float* x  = (const float*)d_in[0];
    const float* wp = (const float*)d_in[1];
    const float* wn = (const float*)d_in[2];
    const float* bp = (const float*)d_in[3];
    const float* bn = (const float*)d_in[4];
    float* out = (float*)d_out;

    const int smem_bytes = 2 * STAGE_BYTES;   // 55296
    cudaFuncSetAttribute(memr_gemm_hmma,
                         cudaFuncAttributeMaxDynamicSharedMemorySize, smem_bytes);

    memr_prep<<<1280, 256>>>(x, wp, wn, bp, bn, out);
    dim3 grid(NOUT / TILE_N, BATCH / MT, KSPLIT);   // 16 x 4 x 2
    memr_gemm_hmma<<<grid, 256, smem_bytes>>>(out);
}